// round 7
// baseline (speedup 1.0000x reference)
#include <cuda_runtime.h>

#define Dd 30
#define H1d 15
#define Tt 512

__device__ __forceinline__ float fast_tanh(float x) {
    // accurate to ~1e-6; clamp avoids inf/inf
    x = fminf(15.f, fmaxf(-15.f, x));
    float e = __expf(2.f * x);
    return __fdividef(e - 1.f, e + 1.f);
}

__global__ void __launch_bounds__(32)
rnn_reg_kernel(const float* __restrict__ x,
               const float* __restrict__ Wih1, const float* __restrict__ Whh1,
               const float* __restrict__ bih1, const float* __restrict__ bhh1,
               const float* __restrict__ Wih2, const float* __restrict__ Whh2,
               const float* __restrict__ bih2, const float* __restrict__ bhh2,
               const float* __restrict__ W1,  const float* __restrict__ b1,
               const float* __restrict__ W2,  const float* __restrict__ b2,
               const float* __restrict__ W3,  const float* __restrict__ b3,
               float* __restrict__ out)
{
    const int lane = threadIdx.x;
    const int b    = blockIdx.x;
    const bool rowv = (lane < Dd);    // owns an RNN row
    const bool mlpv = (lane < H1d);   // owns an MLP row

    // ---- weights in registers: lane j holds row j of each matrix ----
    float Wih1r[Dd], Whh1r[Dd], Wih2r[Dd], Whh2r[Dd], W1r[Dd], W2r[H1d];
#pragma unroll
    for (int k = 0; k < Dd; k++) {
        Wih1r[k] = rowv ? Wih1[lane * Dd + k] : 0.f;
        Whh1r[k] = rowv ? Whh1[lane * Dd + k] : 0.f;
        Wih2r[k] = rowv ? Wih2[lane * Dd + k] : 0.f;
        Whh2r[k] = rowv ? Whh2[lane * Dd + k] : 0.f;
        W1r[k]   = mlpv ? W1[lane * Dd + k]   : 0.f;
    }
#pragma unroll
    for (int k = 0; k < H1d; k++)
        W2r[k] = mlpv ? W2[lane * H1d + k] : 0.f;

    const float W3r  = mlpv ? W3[lane] : 0.f;
    const float bs1r = rowv ? (bih1[lane] + bhh1[lane]) : 0.f;
    const float bs2r = rowv ? (bih2[lane] + bhh2[lane]) : 0.f;
    const float b1r  = mlpv ? b1[lane] : 0.f;
    const float b2r  = mlpv ? b2[lane] : 0.f;
    const float b3v  = b3[0];

    const float* __restrict__ xb = x + (size_t)b * Tt * Dd;
    float* __restrict__ ob = out + (size_t)b * Tt;

    __shared__ float ys[32];

    float h1 = 0.f, h2 = 0.f;
    float xv = rowv ? xb[lane] : 0.f;   // x_t[lane], t=0

    for (int t = 0; t < Tt; t++) {
        // prefetch next step's x (hide DRAM latency behind this step's math)
        float xn = 0.f;
        if (rowv && t + 1 < Tt) xn = __ldg(xb + (size_t)(t + 1) * Dd + lane);

        // ---- RNN layer 1: h1' = tanh(Wih1·x + bs1 + Whh1·h1) ----
        float a0 = bs1r, a1 = 0.f, a2 = 0.f, a3 = 0.f;
#pragma unroll
        for (int k = 0; k < Dd; k += 2) {
            a0 += Wih1r[k]     * __shfl_sync(0xffffffffu, xv, k);
            a1 += Whh1r[k]     * __shfl_sync(0xffffffffu, h1, k);
            a2 += Wih1r[k + 1] * __shfl_sync(0xffffffffu, xv, k + 1);
            a3 += Whh1r[k + 1] * __shfl_sync(0xffffffffu, h1, k + 1);
        }
        const float h1n = fast_tanh((a0 + a1) + (a2 + a3));

        // ---- RNN layer 2: h2' = tanh(Wih2·h1' + bs2 + Whh2·h2) ----
        a0 = bs2r; a1 = 0.f; a2 = 0.f; a3 = 0.f;
#pragma unroll
        for (int k = 0; k < Dd; k += 2) {
            a0 += Wih2r[k]     * __shfl_sync(0xffffffffu, h1n, k);
            a1 += Whh2r[k]     * __shfl_sync(0xffffffffu, h2,  k);
            a2 += Wih2r[k + 1] * __shfl_sync(0xffffffffu, h1n, k + 1);
            a3 += Whh2r[k + 1] * __shfl_sync(0xffffffffu, h2,  k + 1);
        }
        const float h2n = fast_tanh((a0 + a1) + (a2 + a3));
        h1 = h1n;
        h2 = h2n;

        // ---- MLP z1 = tanh(W1·h2 + b1) (lanes 0..14 valid, others exactly 0) ----
        a0 = b1r; a1 = 0.f;
#pragma unroll
        for (int k = 0; k < Dd; k += 2) {
            a0 += W1r[k]     * __shfl_sync(0xffffffffu, h2n, k);
            a1 += W1r[k + 1] * __shfl_sync(0xffffffffu, h2n, k + 1);
        }
        const float z1 = fast_tanh(a0 + a1);

        // ---- MLP z2 = tanh(W2·z1 + b2) ----
        a0 = b2r; a1 = 0.f;
#pragma unroll
        for (int k = 0; k < H1d - 1; k += 2) {
            a0 += W2r[k]     * __shfl_sync(0xffffffffu, z1, k);
            a1 += W2r[k + 1] * __shfl_sync(0xffffffffu, z1, k + 1);
        }
        a0 += W2r[H1d - 1] * __shfl_sync(0xffffffffu, z1, H1d - 1);
        const float z2 = fast_tanh(a0 + a1);

        // ---- y = W3·z2 + b3 : per-lane product, butterfly-reduce over 16 lanes ----
        float p = W3r * z2;   // exactly 0 on lanes >= 15
#pragma unroll
        for (int off = 8; off >= 1; off >>= 1)
            p += __shfl_xor_sync(0xffffffffu, p, off);
        if (lane == 0) ys[t & 31] = p + b3v;

        // ---- coalesced flush every 32 steps ----
        if ((t & 31) == 31) {
            __syncwarp();
            ob[(t - 31) + lane] = ys[lane];
            __syncwarp();
        }

        xv = xn;
    }
}

extern "C" void kernel_launch(void* const* d_in, const int* in_sizes, int n_in,
                              void* d_out, int out_size)
{
    const float* x    = (const float*)d_in[0];
    const float* Wih1 = (const float*)d_in[1];
    const float* Whh1 = (const float*)d_in[2];
    const float* bih1 = (const float*)d_in[3];
    const float* bhh1 = (const float*)d_in[4];
    const float* Wih2 = (const float*)d_in[5];
    const float* Whh2 = (const float*)d_in[6];
    const float* bih2 = (const float*)d_in[7];
    const float* bhh2 = (const float*)d_in[8];
    const float* W1   = (const float*)d_in[9];
    const float* b1   = (const float*)d_in[10];
    const float* W2   = (const float*)d_in[11];
    const float* b2   = (const float*)d_in[12];
    const float* W3   = (const float*)d_in[13];
    const float* b3   = (const float*)d_in[14];

    int B = in_sizes[0] / (Tt * Dd);   // 4096
    rnn_reg_kernel<<<B, 32>>>(x, Wih1, Whh1, bih1, bhh1,
                              Wih2, Whh2, bih2, bhh2,
                              W1, b1, W2, b2, W3, b3,
                              (float*)d_out);
}

// round 8
// speedup vs baseline: 1.2877x; 1.2877x over previous
#include <cuda_runtime.h>

#define Dd 30
#define H1d 15
#define Tt 512

typedef unsigned long long ull;

__device__ __forceinline__ void fma2(ull& d, ull a, ull b) {
    asm("fma.rn.f32x2 %0, %1, %2, %0;" : "+l"(d) : "l"(a), "l"(b));
}
__device__ __forceinline__ ull packf2(float lo, float hi) {
    ull r; asm("mov.b64 %0, {%1, %2};" : "=l"(r) : "f"(lo), "f"(hi)); return r;
}
__device__ __forceinline__ float2 unpackf2(ull v) {
    float2 r; asm("mov.b64 {%0, %1}, %2;" : "=f"(r.x), "=f"(r.y) : "l"(v)); return r;
}

__device__ __forceinline__ float fast_tanh(float x) {
    x = fminf(15.f, fmaxf(-15.f, x));
    float e = __expf(2.f * x);
    return __fdividef(e - 1.f, e + 1.f);
}

// reduce 4 packed accumulators + bias -> scalar
__device__ __forceinline__ float acc_sum4(ull a0, ull a1, ull a2, ull a3, float bias) {
    float2 f0 = unpackf2(a0), f1 = unpackf2(a1), f2 = unpackf2(a2), f3 = unpackf2(a3);
    return ((f0.x + f0.y) + (f1.x + f1.y)) + ((f2.x + f2.y) + (f3.x + f3.y)) + bias;
}
__device__ __forceinline__ float acc_sum2(ull a0, ull a1, float bias) {
    float2 f0 = unpackf2(a0), f1 = unpackf2(a1);
    return (f0.x + f0.y) + (f1.x + f1.y) + bias;
}

__global__ void __launch_bounds__(32)
rnn_f32x2_kernel(const float* __restrict__ x,
                 const float* __restrict__ Wih1, const float* __restrict__ Whh1,
                 const float* __restrict__ bih1, const float* __restrict__ bhh1,
                 const float* __restrict__ Wih2, const float* __restrict__ Whh2,
                 const float* __restrict__ bih2, const float* __restrict__ bhh2,
                 const float* __restrict__ W1,  const float* __restrict__ b1,
                 const float* __restrict__ W2,  const float* __restrict__ b2,
                 const float* __restrict__ W3,  const float* __restrict__ b3,
                 float* __restrict__ out)
{
    __shared__ __align__(16) float xsm[2][32], h1sm[2][32], h2sm[2][32];
    __shared__ __align__(16) float z1sm[32], ys[32];

    const int  lane = threadIdx.x;
    const int  b    = blockIdx.x;
    const bool rowv = (lane < Dd);
    const bool mlpv = (lane < H1d);

    // ---- weights packed as f32x2 pairs in registers (lane j = row j) ----
    ull Wih1p[15], Whh1p[15], Wih2p[15], Whh2p[15], W1p[15], W2p[8];
    {
        // rows are 30 floats = 120B apart -> 8B-aligned, read as ull directly
        const ull* wi1 = (const ull*)(Wih1 + lane * Dd);
        const ull* wh1 = (const ull*)(Whh1 + lane * Dd);
        const ull* wi2 = (const ull*)(Wih2 + lane * Dd);
        const ull* wh2 = (const ull*)(Whh2 + lane * Dd);
        const ull* w1  = (const ull*)(W1   + lane * Dd);
#pragma unroll
        for (int i = 0; i < 15; i++) {
            Wih1p[i] = rowv ? wi1[i] : 0ull;
            Whh1p[i] = rowv ? wh1[i] : 0ull;
            Wih2p[i] = rowv ? wi2[i] : 0ull;
            Whh2p[i] = rowv ? wh2[i] : 0ull;
            W1p[i]   = mlpv ? w1[i]  : 0ull;
        }
        // W2 rows are 60B apart -> scalar loads + pack; pad pair 7 with 0
#pragma unroll
        for (int i = 0; i < 7; i++)
            W2p[i] = mlpv ? packf2(W2[lane * H1d + 2 * i], W2[lane * H1d + 2 * i + 1]) : 0ull;
        W2p[7] = mlpv ? packf2(W2[lane * H1d + 14], 0.f) : 0ull;
    }
    const float W3r  = mlpv ? W3[lane] : 0.f;
    const float bs1r = rowv ? (bih1[lane] + bhh1[lane]) : 0.f;
    const float bs2r = rowv ? (bih2[lane] + bhh2[lane]) : 0.f;
    const float b1r  = mlpv ? b1[lane] : 0.f;
    const float b2r  = mlpv ? b2[lane] : 0.f;
    const float b3v  = b3[0];

    const float* __restrict__ xb = x + (size_t)b * Tt * Dd;
    float* __restrict__ ob = out + (size_t)b * Tt;

    // ---- init state + x pipeline ----
    h1sm[0][lane] = 0.f; h1sm[1][lane] = 0.f;
    h2sm[0][lane] = 0.f; h2sm[1][lane] = 0.f;
    z1sm[lane] = 0.f;
    xsm[0][lane] = rowv ? __ldg(xb + lane) : 0.f;
    float xnA = rowv ? __ldg(xb + Dd + lane) : 0.f;      // x_{t+1}
    float xnB = rowv ? __ldg(xb + 2 * Dd + lane) : 0.f;  // x_{t+2}
    __syncwarp();

#pragma unroll 2
    for (int t = 0; t < Tt; t++) {
        const int p = t & 1;

        // ---- layer 1: h1' = tanh(Wih1·x_t + Whh1·h1 + bs1) ----
        {
            const ulonglong2* xp = (const ulonglong2*)xsm[p];
            const ulonglong2* hp = (const ulonglong2*)h1sm[p];
            ull a0 = 0, a1 = 0, a2 = 0, a3 = 0;
#pragma unroll
            for (int i = 0; i < 7; i++) {
                ulonglong2 xv = xp[i], hv = hp[i];
                fma2(a0, Wih1p[2 * i],     xv.x);
                fma2(a1, Whh1p[2 * i],     hv.x);
                fma2(a2, Wih1p[2 * i + 1], xv.y);
                fma2(a3, Whh1p[2 * i + 1], hv.y);
            }
            fma2(a0, Wih1p[14], ((const ull*)xsm[p])[14]);
            fma2(a1, Whh1p[14], ((const ull*)h1sm[p])[14]);
            h1sm[1 - p][lane] = fast_tanh(acc_sum4(a0, a1, a2, a3, bs1r));
        }
        __syncwarp();

        // ---- layer 2: h2' = tanh(Wih2·h1' + Whh2·h2 + bs2) ----
        {
            const ulonglong2* ip = (const ulonglong2*)h1sm[1 - p];
            const ulonglong2* hp = (const ulonglong2*)h2sm[p];
            ull a0 = 0, a1 = 0, a2 = 0, a3 = 0;
#pragma unroll
            for (int i = 0; i < 7; i++) {
                ulonglong2 iv = ip[i], hv = hp[i];
                fma2(a0, Wih2p[2 * i],     iv.x);
                fma2(a1, Whh2p[2 * i],     hv.x);
                fma2(a2, Wih2p[2 * i + 1], iv.y);
                fma2(a3, Whh2p[2 * i + 1], hv.y);
            }
            fma2(a0, Wih2p[14], ((const ull*)h1sm[1 - p])[14]);
            fma2(a1, Whh2p[14], ((const ull*)h2sm[p])[14]);
            h2sm[1 - p][lane] = fast_tanh(acc_sum4(a0, a1, a2, a3, bs2r));
        }
        __syncwarp();

        // ---- MLP z1 = tanh(W1·h2' + b1) (rows 0..14 real; others exact 0) ----
        {
            const ulonglong2* ip = (const ulonglong2*)h2sm[1 - p];
            ull a0 = 0, a1 = 0;
#pragma unroll
            for (int i = 0; i < 7; i++) {
                ulonglong2 iv = ip[i];
                fma2(a0, W1p[2 * i],     iv.x);
                fma2(a1, W1p[2 * i + 1], iv.y);
            }
            fma2(a0, W1p[14], ((const ull*)h2sm[1 - p])[14]);
            z1sm[lane] = fast_tanh(acc_sum2(a0, a1, b1r));
        }
        __syncwarp();

        // ---- MLP z2 = tanh(W2·z1 + b2), then y = W3·z2 + b3 ----
        {
            const ulonglong2* ip = (const ulonglong2*)z1sm;
            ull a0 = 0, a1 = 0;
#pragma unroll
            for (int i = 0; i < 4; i++) {
                ulonglong2 iv = ip[i];
                fma2(a0, W2p[2 * i],     iv.x);
                fma2(a1, W2p[2 * i + 1], iv.y);
            }
            const float z2 = fast_tanh(acc_sum2(a0, a1, b2r));
            float s = W3r * z2;  // exact 0 on lanes >= 15
#pragma unroll
            for (int off = 16; off >= 1; off >>= 1)
                s += __shfl_xor_sync(0xffffffffu, s, off);
            if (lane == 0) ys[t & 31] = s + b3v;
        }

        // ---- stage x_{t+1}, refill prefetch pipeline ----
        xsm[1 - p][lane] = xnA;
        xnA = xnB;
        xnB = (rowv && t + 3 < Tt) ? __ldg(xb + (size_t)(t + 3) * Dd + lane) : 0.f;
        __syncwarp();

        // ---- coalesced output flush every 32 steps ----
        if ((t & 31) == 31)
            ob[(t - 31) + lane] = ys[lane];
    }
}

extern "C" void kernel_launch(void* const* d_in, const int* in_sizes, int n_in,
                              void* d_out, int out_size)
{
    const float* x    = (const float*)d_in[0];
    const float* Wih1 = (const float*)d_in[1];
    const float* Whh1 = (const float*)d_in[2];
    const float* bih1 = (const float*)d_in[3];
    const float* bhh1 = (const float*)d_in[4];
    const float* Wih2 = (const float*)d_in[5];
    const float* Whh2 = (const float*)d_in[6];
    const float* bih2 = (const float*)d_in[7];
    const float* bhh2 = (const float*)d_in[8];
    const float* W1   = (const float*)d_in[9];
    const float* b1   = (const float*)d_in[10];
    const float* W2   = (const float*)d_in[11];
    const float* b2   = (const float*)d_in[12];
    const float* W3   = (const float*)d_in[13];
    const float* b3   = (const float*)d_in[14];

    int B = in_sizes[0] / (Tt * Dd);   // 4096
    rnn_f32x2_kernel<<<B, 32>>>(x, Wih1, Whh1, bih1, bhh1,
                                Wih2, Whh2, bih2, bhh2,
                                W1, b1, W2, b2, W3, b3,
                                (float*)d_out);
}

// round 10
// speedup vs baseline: 1.3319x; 1.0343x over previous
#include <cuda_runtime.h>

#define Dd 30
#define H1d 15
#define Tt 512

typedef unsigned long long ull;

__device__ __forceinline__ void fma2(ull& d, ull a, ull b) {
    asm("fma.rn.f32x2 %0, %1, %2, %0;" : "+l"(d) : "l"(a), "l"(b));
}
__device__ __forceinline__ ull packf2(float lo, float hi) {
    ull r; asm("mov.b64 %0, {%1, %2};" : "=l"(r) : "f"(lo), "f"(hi)); return r;
}
__device__ __forceinline__ float2 unpackf2(ull v) {
    float2 r; asm("mov.b64 {%0, %1}, %2;" : "=f"(r.x), "=f"(r.y) : "l"(v)); return r;
}

__device__ __forceinline__ float fast_tanh(float x) {
    x = fminf(15.f, fmaxf(-15.f, x));
    float e = __expf(2.f * x);
    return __fdividef(e - 1.f, e + 1.f);
}

__device__ __forceinline__ float acc_sum4(ull a0, ull a1, ull a2, ull a3, float bias) {
    float2 f0 = unpackf2(a0), f1 = unpackf2(a1), f2 = unpackf2(a2), f3 = unpackf2(a3);
    return ((f0.x + f0.y) + (f1.x + f1.y)) + ((f2.x + f2.y) + (f3.x + f3.y)) + bias;
}
__device__ __forceinline__ float acc_sum2(ull a0, ull a1, float bias) {
    float2 f0 = unpackf2(a0), f1 = unpackf2(a1);
    return (f0.x + f0.y) + (f1.x + f1.y) + bias;
}

#define EPW 2   // batch elements per warp (independent ILP chains)

__global__ void __launch_bounds__(32)
rnn_ilp2_kernel(const float* __restrict__ x,
                const float* __restrict__ Wih1, const float* __restrict__ Whh1,
                const float* __restrict__ bih1, const float* __restrict__ bhh1,
                const float* __restrict__ Wih2, const float* __restrict__ Whh2,
                const float* __restrict__ bih2, const float* __restrict__ bhh2,
                const float* __restrict__ W1,  const float* __restrict__ b1,
                const float* __restrict__ W2,  const float* __restrict__ b2,
                const float* __restrict__ W3,  const float* __restrict__ b3,
                float* __restrict__ out)
{
    __shared__ __align__(16) float xsm[EPW][2][32], h1sm[EPW][2][32], h2sm[EPW][2][32];
    __shared__ __align__(16) float z1sm[EPW][32], ys[EPW][32];

    const int  lane = threadIdx.x;
    const bool rowv = (lane < Dd);
    const bool mlpv = (lane < H1d);

    // ---- weights packed as f32x2 pairs in registers (lane j = row j), shared by both elems ----
    ull Wih1p[15], Whh1p[15], Wih2p[15], Whh2p[15], W1p[15], W2p[8];
    {
        const ull* wi1 = (const ull*)(Wih1 + lane * Dd);
        const ull* wh1 = (const ull*)(Whh1 + lane * Dd);
        const ull* wi2 = (const ull*)(Wih2 + lane * Dd);
        const ull* wh2 = (const ull*)(Whh2 + lane * Dd);
        const ull* w1  = (const ull*)(W1   + lane * Dd);
#pragma unroll
        for (int i = 0; i < 15; i++) {
            Wih1p[i] = rowv ? wi1[i] : 0ull;
            Whh1p[i] = rowv ? wh1[i] : 0ull;
            Wih2p[i] = rowv ? wi2[i] : 0ull;
            Whh2p[i] = rowv ? wh2[i] : 0ull;
            W1p[i]   = mlpv ? w1[i]  : 0ull;
        }
#pragma unroll
        for (int i = 0; i < 7; i++)
            W2p[i] = mlpv ? packf2(W2[lane * H1d + 2 * i], W2[lane * H1d + 2 * i + 1]) : 0ull;
        W2p[7] = mlpv ? packf2(W2[lane * H1d + 14], 0.f) : 0ull;
    }
    const float W3r  = mlpv ? W3[lane] : 0.f;
    const float bs1r = rowv ? (bih1[lane] + bhh1[lane]) : 0.f;
    const float bs2r = rowv ? (bih2[lane] + bhh2[lane]) : 0.f;
    const float b1r  = mlpv ? b1[lane] : 0.f;
    const float b2r  = mlpv ? b2[lane] : 0.f;
    const float b3v  = b3[0];

    const int b0 = blockIdx.x * EPW;
    const float* __restrict__ xbe[EPW];
    float* __restrict__ obe[EPW];
#pragma unroll
    for (int e = 0; e < EPW; e++) {
        xbe[e] = x + (size_t)(b0 + e) * Tt * Dd;
        obe[e] = out + (size_t)(b0 + e) * Tt;
    }

    // ---- init state + x prefetch pipeline (depth 2 per elem) ----
    float xnA[EPW], xnB[EPW];
#pragma unroll
    for (int e = 0; e < EPW; e++) {
        h1sm[e][0][lane] = 0.f; h1sm[e][1][lane] = 0.f;
        h2sm[e][0][lane] = 0.f; h2sm[e][1][lane] = 0.f;
        z1sm[e][lane] = 0.f;
        xsm[e][0][lane] = rowv ? __ldg(xbe[e] + lane) : 0.f;
        xnA[e] = rowv ? __ldg(xbe[e] + Dd + lane) : 0.f;
        xnB[e] = rowv ? __ldg(xbe[e] + 2 * Dd + lane) : 0.f;
    }
    __syncwarp();

    for (int t = 0; t < Tt; t++) {
        const int p = t & 1;

        // ---- layer 1 (both elems, independent chains) ----
#pragma unroll
        for (int e = 0; e < EPW; e++) {
            const ulonglong2* xp = (const ulonglong2*)xsm[e][p];
            const ulonglong2* hp = (const ulonglong2*)h1sm[e][p];
            ull a0 = 0, a1 = 0, a2 = 0, a3 = 0;
#pragma unroll
            for (int i = 0; i < 7; i++) {
                ulonglong2 xv = xp[i], hv = hp[i];
                fma2(a0, Wih1p[2 * i],     xv.x);
                fma2(a1, Whh1p[2 * i],     hv.x);
                fma2(a2, Wih1p[2 * i + 1], xv.y);
                fma2(a3, Whh1p[2 * i + 1], hv.y);
            }
            fma2(a0, Wih1p[14], ((const ull*)xsm[e][p])[14]);
            fma2(a1, Whh1p[14], ((const ull*)h1sm[e][p])[14]);
            h1sm[e][1 - p][lane] = fast_tanh(acc_sum4(a0, a1, a2, a3, bs1r));
        }
        __syncwarp();

        // ---- layer 2 ----
#pragma unroll
        for (int e = 0; e < EPW; e++) {
            const ulonglong2* ip = (const ulonglong2*)h1sm[e][1 - p];
            const ulonglong2* hp = (const ulonglong2*)h2sm[e][p];
            ull a0 = 0, a1 = 0, a2 = 0, a3 = 0;
#pragma unroll
            for (int i = 0; i < 7; i++) {
                ulonglong2 iv = ip[i], hv = hp[i];
                fma2(a0, Wih2p[2 * i],     iv.x);
                fma2(a1, Whh2p[2 * i],     hv.x);
                fma2(a2, Wih2p[2 * i + 1], iv.y);
                fma2(a3, Whh2p[2 * i + 1], hv.y);
            }
            fma2(a0, Wih2p[14], ((const ull*)h1sm[e][1 - p])[14]);
            fma2(a1, Whh2p[14], ((const ull*)h2sm[e][p])[14]);
            h2sm[e][1 - p][lane] = fast_tanh(acc_sum4(a0, a1, a2, a3, bs2r));
        }
        __syncwarp();

        // ---- MLP z1 ----
#pragma unroll
        for (int e = 0; e < EPW; e++) {
            const ulonglong2* ip = (const ulonglong2*)h2sm[e][1 - p];
            ull a0 = 0, a1 = 0;
#pragma unroll
            for (int i = 0; i < 7; i++) {
                ulonglong2 iv = ip[i];
                fma2(a0, W1p[2 * i],     iv.x);
                fma2(a1, W1p[2 * i + 1], iv.y);
            }
            fma2(a0, W1p[14], ((const ull*)h2sm[e][1 - p])[14]);
            z1sm[e][lane] = fast_tanh(acc_sum2(a0, a1, b1r));
        }
        __syncwarp();

        // ---- MLP z2 + y ----
#pragma unroll
        for (int e = 0; e < EPW; e++) {
            const ulonglong2* ip = (const ulonglong2*)z1sm[e];
            ull a0 = 0, a1 = 0;
#pragma unroll
            for (int i = 0; i < 4; i++) {
                ulonglong2 iv = ip[i];
                fma2(a0, W2p[2 * i],     iv.x);
                fma2(a1, W2p[2 * i + 1], iv.y);
            }
            const float z2 = fast_tanh(acc_sum2(a0, a1, b2r));
            float s = W3r * z2;   // exact 0 on lanes >= 15 (and lane 15)
#pragma unroll
            for (int off = 8; off >= 1; off >>= 1)
                s += __shfl_xor_sync(0xffffffffu, s, off);
            if (lane == 0) ys[e][t & 31] = s + b3v;
        }

        // ---- stage x_{t+1}, refill prefetch ----
#pragma unroll
        for (int e = 0; e < EPW; e++) {
            xsm[e][1 - p][lane] = xnA[e];
            xnA[e] = xnB[e];
            xnB[e] = (rowv && t + 3 < Tt) ? __ldg(xbe[e] + (size_t)(t + 3) * Dd + lane) : 0.f;
        }
        __syncwarp();

        // ---- coalesced flush every 32 steps ----
        if ((t & 31) == 31) {
#pragma unroll
            for (int e = 0; e < EPW; e++)
                obe[e][(t - 31) + lane] = ys[e][lane];
        }
    }
}

extern "C" void kernel_launch(void* const* d_in, const int* in_sizes, int n_in,
                              void* d_out, int out_size)
{
    const float* x    = (const float*)d_in[0];
    const float* Wih1 = (const float*)d_in[1];
    const float* Whh1 = (const float*)d_in[2];
    const float* bih1 = (const float*)d_in[3];
    const float* bhh1 = (const float*)d_in[4];
    const float* Wih2 = (const float*)d_in[5];
    const float* Whh2 = (const float*)d_in[6];
    const float* bih2 = (const float*)d_in[7];
    const float* bhh2 = (const float*)d_in[8];
    const float* W1   = (const float*)d_in[9];
    const float* b1   = (const float*)d_in[10];
    const float* W2   = (const float*)d_in[11];
    const float* b2   = (const float*)d_in[12];
    const float* W3   = (const float*)d_in[13];
    const float* b3   = (const float*)d_in[14];

    int B = in_sizes[0] / (Tt * Dd);   // 4096
    rnn_ilp2_kernel<<<B / EPW, 32>>>(x, Wih1, Whh1, bih1, bhh1,
                                     Wih2, Whh2, bih2, bhh2,
                                     W1, b1, W2, b2, W3, b3,
                                     (float*)d_out);
}